// round 17
// baseline (speedup 1.0000x reference)
#include <cuda_runtime.h>
#include <math.h>

#define B_DIM 64
#define K_DIM 128
#define H_DIM 64
#define W_DIM 64
#define PLANE (H_DIM * W_DIM)          // 4096 floats
#define N_PLANES (B_DIM * K_DIM)       // 8192
#define N_BOXES 256
#define N_WORK (N_PLANES + N_BOXES)    // 8448 working blocks
#define N_BLOCKS (N_WORK + 1)          // +1 waiter block (scheduled last)
#define ALPHA 1.0f
#define BETA 0.5f
#define NPART 32
#define PART_STRIDE 32                 // 128B between accumulator slots

// Zero-initialized device globals; waiter resets them each run.
__device__ float g_cls_parts[NPART * PART_STRIDE];
__device__ float g_loc_parts[NPART * PART_STRIDE];
__device__ unsigned int g_done_count;

__device__ __forceinline__ float softplus_f(float x) {
    float ax = fabsf(x);
    return log1pf(expf(-ax)) + fmaxf(x, 0.0f);
}

__device__ __forceinline__ unsigned int ld_acquire_gpu(const unsigned int* addr) {
    unsigned int v;
    asm volatile("ld.acquire.gpu.global.u32 %0, [%1];" : "=r"(v) : "l"(addr));
    return v;
}
__device__ __forceinline__ void red_add_u32(unsigned int* addr, unsigned int v) {
    asm volatile("red.global.add.u32 [%0], %1;" :: "l"(addr), "r"(v) : "memory");
}

// Part-accumulate + completion signal with hardware-enforced ordering:
// the RETURNING atomicAdd completes at L2 before 'old' is available; the
// counter increment is data-dependent on 'old' ((sign>>31)+1 == 1 for our
// non-negative partials, but ptxas cannot fold it), so the counter RED is
// issued strictly after the part value is globally visible. No fences.
__device__ __forceinline__ void part_add_then_signal(float* slot, float val) {
    float old = atomicAdd(slot, val);                      // returning ATOMG
    unsigned int inc = (__float_as_uint(old) >> 31) + 1u;  // == 1, depends on old
    red_add_u32(&g_done_count, inc);                       // fire-and-forget
}

__global__ __launch_bounds__(256) void fused_loss_kernel(
    const float* __restrict__ cams,
    const float* __restrict__ concepts_gt,
    const int* __restrict__ box_b,
    const int* __restrict__ box_c,
    const int* __restrict__ y0v,
    const int* __restrict__ y1v,
    const int* __restrict__ x0v,
    const int* __restrict__ x1v,
    float* __restrict__ out)
{
    int t = threadIdx.x;
    int wid = t >> 5, lid = t & 31;
    __shared__ float s0[8], s1[8];

    if (blockIdx.x == N_WORK) {
        // ================= waiter block (one warp active) =================
        if (wid == 0) {
            if (lid == 0) {
                while (ld_acquire_gpu(&g_done_count) != N_WORK)
                    __nanosleep(128);
            }
            __syncwarp();
            // Returning atomics read the coherent L2 values.
            float cls = atomicAdd(&g_cls_parts[lid * PART_STRIDE], 0.0f);
            float loc = atomicAdd(&g_loc_parts[lid * PART_STRIDE], 0.0f);
            g_cls_parts[lid * PART_STRIDE] = 0.0f;   // reset for replay
            g_loc_parts[lid * PART_STRIDE] = 0.0f;
#pragma unroll
            for (int off = 16; off > 0; off >>= 1) {
                cls += __shfl_xor_sync(0xFFFFFFFFu, cls, off);
                loc += __shfl_xor_sync(0xFFFFFFFFu, loc, off);
            }
            if (lid == 0) {
                out[0] = ALPHA * (cls / (float)N_PLANES) + BETA * (loc / (float)N_BOXES);
                g_done_count = 0u;                   // reset for replay
            }
        }
        return;
    }

    if (blockIdx.x < N_BOXES) {
        // ---------------- loc block: one box ----------------
        int box = blockIdx.x;
        int b = box_b[box];
        int c = box_c[box];
        int y0 = y0v[box], y1 = y1v[box], x0 = x0v[box], x1 = x1v[box];

        const float4* p = reinterpret_cast<const float4*>(
            cams + ((size_t)b * K_DIM + c) * PLANE);

        float inside = 0.0f, outside = 0.0f;
#pragma unroll
        for (int i = 0; i < 4; i++) {
            int u = i * 256 + t;        // float4 index within plane [0,1024)
            float4 v = p[u];
            int row = u >> 4;           // 16 float4 per row (W=64)
            int col0 = (u & 15) << 2;
            float vals[4] = {v.x, v.y, v.z, v.w};
            bool rin = (row >= y0) && (row < y1);
#pragma unroll
            for (int j = 0; j < 4; j++) {
                int col = col0 + j;
                float e = __expf(-vals[j]);
                float s = __fdividef(1.0f, 1.0f + e);
                bool in = rin && (col >= x0) && (col < x1);
                float d = s - 1.0f;
                if (in) inside += d * d;
                else    outside += s * s;
            }
        }
#pragma unroll
        for (int off = 16; off > 0; off >>= 1) {
            inside  += __shfl_xor_sync(0xFFFFFFFFu, inside, off);
            outside += __shfl_xor_sync(0xFFFFFFFFu, outside, off);
        }
        if (lid == 0) { s0[wid] = inside; s1[wid] = outside; }
        __syncthreads();
        if (t == 0) {
            float ti = 0.0f, to = 0.0f;
#pragma unroll
            for (int w = 0; w < 8; w++) { ti += s0[w]; to += s1[w]; }
            float area = (float)((y1 - y0) * (x1 - x0));
            const float eps = 1e-6f;
            float loss = ti / (area + eps) + to / ((float)PLANE - area + eps);
            part_add_then_signal(&g_loc_parts[(box & (NPART - 1)) * PART_STRIDE], loss);
        }
    } else {
        // ---------------- cls block: one (b,k) plane ----------------
        int plane = blockIdx.x - N_BOXES;
        const float4* p = reinterpret_cast<const float4*>(cams + (size_t)plane * PLANE);

        float m = -INFINITY;
#pragma unroll
        for (int i = 0; i < 4; i++) {
            float4 v = p[i * 256 + t];
            m = fmaxf(m, fmaxf(fmaxf(v.x, v.y), fmaxf(v.z, v.w)));
        }
#pragma unroll
        for (int off = 16; off > 0; off >>= 1)
            m = fmaxf(m, __shfl_xor_sync(0xFFFFFFFFu, m, off));
        if (lid == 0) s0[wid] = m;
        __syncthreads();
        if (t == 0) {
            float bm = s0[0];
#pragma unroll
            for (int w = 1; w < 8; w++) bm = fmaxf(bm, s0[w]);
            float y = concepts_gt[plane];
            float bce = y * softplus_f(-bm) + (1.0f - y) * softplus_f(bm);
            part_add_then_signal(&g_cls_parts[(plane & (NPART - 1)) * PART_STRIDE], bce);
        }
    }
}

extern "C" void kernel_launch(void* const* d_in, const int* in_sizes, int n_in,
                              void* d_out, int out_size) {
    const float* cams        = (const float*)d_in[0];
    const float* concepts_gt = (const float*)d_in[1];
    const int*   box_b       = (const int*)d_in[2];
    const int*   box_c       = (const int*)d_in[3];
    const int*   y0          = (const int*)d_in[4];
    const int*   y1          = (const int*)d_in[5];
    const int*   x0          = (const int*)d_in[6];
    const int*   x1          = (const int*)d_in[7];
    float* out = (float*)d_out;

    fused_loss_kernel<<<N_BLOCKS, 256>>>(cams, concepts_gt, box_b, box_c,
                                         y0, y1, x0, x1, out);
}